// round 15
// baseline (speedup 1.0000x reference)
#include <cuda_runtime.h>
#include <cuda_fp16.h>
#include <math.h>
#include <stdint.h>

#define Bn  64
#define Tn  1380
#define XDn 96
#define HDn 192
#define CNn 345
#define NUT 11            // ceil(1380/128) u-tiles

// SCALE = 1/sqrt(96*192)
#define SCALEF 0.007365695637359841f
#define NEGBIG -1e30f

typedef unsigned long long u64;

// ---- packed fp32x2 helpers (exact fp32 per lane) ---------------------------
__device__ __forceinline__ u64 pack2(float x, float y) {
    u64 r; asm("mov.b64 %0, {%1, %2};" : "=l"(r) : "f"(x), "f"(y)); return r;
}
__device__ __forceinline__ float2 unpack2(u64 v) {
    float lo, hi; asm("mov.b64 {%0, %1}, %2;" : "=f"(lo), "=f"(hi) : "l"(v));
    return make_float2(lo, hi);
}
__device__ __forceinline__ void fma2(u64& d, u64 a, u64 b) {
    asm("fma.rn.f32x2 %0, %1, %2, %0;" : "+l"(d) : "l"(a), "l"(b));
}

// ---- fp16 m16n8k16 mma (fp32 accum) ----------------------------------------
__device__ __forceinline__ void mma16(float* d, const uint32_t* a,
                                      const uint32_t* b) {
    asm volatile(
        "mma.sync.aligned.m16n8k16.row.col.f32.f16.f16.f32 "
        "{%0,%1,%2,%3}, {%4,%5,%6,%7}, {%8,%9}, {%0,%1,%2,%3};"
        : "+f"(d[0]), "+f"(d[1]), "+f"(d[2]), "+f"(d[3])
        : "r"(a[0]), "r"(a[1]), "r"(a[2]), "r"(a[3]), "r"(b[0]), "r"(b[1]));
}
// split x into hi (rn fp16) and lo = rn16(x - hi)
__device__ __forceinline__ void split16(float x, __half& h, __half& l) {
    h = __float2half_rn(x);
    l = __float2half_rn(x - __half2float(h));
}

// Scratch (allocation-free rule: __device__ globals)
__device__ float g_Z[(size_t)Bn * CNn * XDn];
__device__ float g_Y[(size_t)Bn * CNn * HDn];
__device__ float g_L[(size_t)Bn * CNn * Tn];   // holds Pu = exp(L - m_tile)
__device__ float g_pm[(size_t)Bn * CNn * NUT];
__device__ float g_ps[(size_t)Bn * CNn * NUT];
__device__ float g_mx[Bn * CNn];
__device__ float g_inv[Bn * CNn];

// guarded float4 row load (Tn tail)
__device__ __forceinline__ float4 ld4g(const float* row, int t, bool ok) {
    float4 v = make_float4(0.f, 0.f, 0.f, 0.f);
    if (ok) {
        if (t + 3 < Tn) v = *(const float4*)(row + t);
        else {
            if (t     < Tn) v.x = row[t];
            if (t + 1 < Tn) v.y = row[t + 1];
            if (t + 2 < Tn) v.z = row[t + 2];
            if (t + 3 < Tn) v.w = row[t + 3];
        }
    }
    return v;
}

// ---------------------------------------------------------------------------
// Z[b,c,x] = sum_t W2[c,t] * X[b,t,x]   (unchanged FFMA2 version)
// ---------------------------------------------------------------------------
__global__ __launch_bounds__(256) void z_kernel(const float* __restrict__ X,
                                                const float* __restrict__ W2) {
    int b  = blockIdx.y;
    int c0 = blockIdx.x * 128;
    __shared__ float As[16][132];
    __shared__ float Bs[16][100];
    int tid = threadIdx.x, tx = tid & 15, ty = tid >> 4;
    const float* Xb = X + (size_t)b * Tn * XDn;

    int rf = tid >> 1;
    int k4 = (tid & 1) * 8;
    int ca = c0 + rf;
    bool cav = ca < CNn;
    const float* W2r = W2 + (size_t)(cav ? ca : 0) * Tn;

    int brow[3], bx2[3];
    #pragma unroll
    for (int i = 0; i < 3; i++) {
        int l = tid + 256 * i;
        brow[i] = l / 48;
        bx2[i]  = (l % 48) * 2;
    }

    float4 wa0 = ld4g(W2r, k4,     cav);
    float4 wa1 = ld4g(W2r, k4 + 4, cav);
    float2 xb[3];
    #pragma unroll
    for (int i = 0; i < 3; i++) {
        int t = brow[i];
        xb[i] = (t < Tn) ? *(const float2*)(Xb + (size_t)t * XDn + bx2[i])
                         : make_float2(0.f, 0.f);
    }

    u64 acc2[8][3] = {};

    for (int k0 = 0; k0 < Tn; k0 += 16) {
        As[k4 + 0][rf] = wa0.x; As[k4 + 1][rf] = wa0.y;
        As[k4 + 2][rf] = wa0.z; As[k4 + 3][rf] = wa0.w;
        As[k4 + 4][rf] = wa1.x; As[k4 + 5][rf] = wa1.y;
        As[k4 + 6][rf] = wa1.z; As[k4 + 7][rf] = wa1.w;
        #pragma unroll
        for (int i = 0; i < 3; i++)
            *(float2*)&Bs[brow[i]][bx2[i]] = xb[i];
        __syncthreads();

        if (k0 + 16 < Tn) {
            wa0 = ld4g(W2r, k0 + 16 + k4,     cav);
            wa1 = ld4g(W2r, k0 + 16 + k4 + 4, cav);
            #pragma unroll
            for (int i = 0; i < 3; i++) {
                int t = k0 + 16 + brow[i];
                xb[i] = (t < Tn) ? *(const float2*)(Xb + (size_t)t * XDn + bx2[i])
                                 : make_float2(0.f, 0.f);
            }
        }

        #pragma unroll
        for (int k = 0; k < 16; k++) {
            float4 a0 = *(const float4*)&As[k][ty * 4];
            float4 a1 = *(const float4*)&As[k][64 + ty * 4];
            u64 bp[3];
            bp[0] = *(const u64*)&Bs[k][tx * 6 + 0];
            bp[1] = *(const u64*)&Bs[k][tx * 6 + 2];
            bp[2] = *(const u64*)&Bs[k][tx * 6 + 4];
            float av[8] = {a0.x, a0.y, a0.z, a0.w, a1.x, a1.y, a1.z, a1.w};
            u64 ap[8];
            #pragma unroll
            for (int i = 0; i < 8; i++) ap[i] = pack2(av[i], av[i]);
            #pragma unroll
            for (int i = 0; i < 8; i++)
                #pragma unroll
                for (int j = 0; j < 3; j++)
                    fma2(acc2[i][j], ap[i], bp[j]);
        }
        __syncthreads();
    }

    float* Zb = g_Z + (size_t)b * CNn * XDn;
    #pragma unroll
    for (int i = 0; i < 8; i++) {
        int c = c0 + ((i < 4) ? (ty * 4 + i) : (64 + ty * 4 + i - 4));
        if (c < CNn) {
            float* zp = Zb + (size_t)c * XDn + tx * 6;
            #pragma unroll
            for (int j = 0; j < 3; j++) {
                float2 f = unpack2(acc2[i][j]);
                *(float2*)(zp + 2 * j) = f;
            }
        }
    }
}

// ---------------------------------------------------------------------------
// Y[b,c,h] = SCALE * sum_x Z[b,c,x] * W1[x,h]   (unchanged)
// ---------------------------------------------------------------------------
__global__ __launch_bounds__(192) void y_kernel(const float* __restrict__ W1) {
    int b  = blockIdx.y;
    int c0 = blockIdx.x * 8;
    __shared__ float Zs[8][96];
    const float* Zb = g_Z + (size_t)b * CNn * XDn;
    for (int l = threadIdx.x; l < 8 * 96; l += 192) {
        int r = l / 96, x = l % 96;
        int c = c0 + r;
        Zs[r][x] = (c < CNn) ? Zb[(size_t)c * XDn + x] : 0.f;
    }
    __syncthreads();
    int h = threadIdx.x;
    float acc[8] = {};
    for (int x = 0; x < 96; x++) {
        float w = W1[(size_t)x * HDn + h];
        #pragma unroll
        for (int r = 0; r < 8; r++) acc[r] = fmaf(Zs[r][x], w, acc[r]);
    }
    float* Yb = g_Y + (size_t)b * CNn * HDn;
    #pragma unroll
    for (int r = 0; r < 8; r++) {
        int c = c0 + r;
        if (c < CNn) Yb[(size_t)c * HDn + h] = acc[r] * SCALEF;
    }
}

// ===========================================================================
// l_mma_kernel: L = Y @ H^T via mma.sync m16n8k16 FP16 split-3.
// hi/lo pre-split into smem half tiles at fill; inner loop = LDS + MMA only.
// Block 128c x 128u, 8 warps (4 c-dir x 2 u-dir), warp 32x64 = 2x8 atoms.
// Epilogue: per-tile (max,sumexp) partials + stores Pu = exp(L - m_tile).
// ===========================================================================
#define LP  200                                   // half pitch (192 + 8)
#define LSM_BYTES (4 * 128 * LP * 2)              // 204800

__global__ __launch_bounds__(256) void l_mma_kernel(const float* __restrict__ H) {
    extern __shared__ char smraw[];
    __half* Yhi = (__half*)smraw;
    __half* Ylo = Yhi + 128 * LP;
    __half* Hhi = Ylo + 128 * LP;
    __half* Hlo = Hhi + 128 * LP;
    int b  = blockIdx.z;
    int c0 = blockIdx.y * 128;
    int u0 = blockIdx.x * 128;
    int ut = blockIdx.x;
    int tid = threadIdx.x;
    int wid = tid >> 5, lane = tid & 31, gid = lane >> 2, tg = lane & 3;
    int wm = wid & 3, wn = wid >> 2;     // c: wm*32, u: wn*64

    const float* Yb = g_Y + (size_t)b * CNn * HDn;
    const float* Hb = H + (size_t)b * Tn * HDn;
    const float4 z4 = make_float4(0.f, 0.f, 0.f, 0.f);

    #pragma unroll
    for (int i = 0; i < 24; i++) {
        int idx = tid + 256 * i;
        int r = idx / 48, kk = (idx % 48) * 4;
        int c = c0 + r;
        float4 v = (c < CNn) ? *(const float4*)(Yb + (size_t)c * HDn + kk) : z4;
        __half hx, lx, hy, ly, hz, lz, hw, lw;
        split16(v.x, hx, lx); split16(v.y, hy, ly);
        split16(v.z, hz, lz); split16(v.w, hw, lw);
        *(__half2*)&Yhi[r * LP + kk]     = __halves2half2(hx, hy);
        *(__half2*)&Yhi[r * LP + kk + 2] = __halves2half2(hz, hw);
        *(__half2*)&Ylo[r * LP + kk]     = __halves2half2(lx, ly);
        *(__half2*)&Ylo[r * LP + kk + 2] = __halves2half2(lz, lw);
        int u = u0 + r;
        float4 w = (u < Tn) ? *(const float4*)(Hb + (size_t)u * HDn + kk) : z4;
        split16(w.x, hx, lx); split16(w.y, hy, ly);
        split16(w.z, hz, lz); split16(w.w, hw, lw);
        *(__half2*)&Hhi[r * LP + kk]     = __halves2half2(hx, hy);
        *(__half2*)&Hhi[r * LP + kk + 2] = __halves2half2(hz, hw);
        *(__half2*)&Hlo[r * LP + kk]     = __halves2half2(lx, ly);
        *(__half2*)&Hlo[r * LP + kk + 2] = __halves2half2(lz, lw);
    }
    __syncthreads();

    float d[2][8][4];
    #pragma unroll
    for (int i = 0; i < 2; i++)
        #pragma unroll
        for (int j = 0; j < 8; j++)
            #pragma unroll
            for (int q = 0; q < 4; q++) d[i][j][q] = 0.f;

    const __half* Yhp = Yhi + (wm * 32 + gid) * LP;
    const __half* Ylp = Ylo + (wm * 32 + gid) * LP;
    const __half* Hhp = Hhi + (wn * 64 + gid) * LP;
    const __half* Hlp = Hlo + (wn * 64 + gid) * LP;

    #pragma unroll 1
    for (int kk = 0; kk < 12; kk++) {
        int k2 = kk * 16 + 2 * tg;
        uint32_t ahi[2][4], alo[2][4], bhi[8][2], blo[8][2];
        #pragma unroll
        for (int i = 0; i < 2; i++) {
            int o = i * 16 * LP + k2;
            ahi[i][0] = *(const uint32_t*)&Yhp[o];
            ahi[i][1] = *(const uint32_t*)&Yhp[o + 8 * LP];
            ahi[i][2] = *(const uint32_t*)&Yhp[o + 8];
            ahi[i][3] = *(const uint32_t*)&Yhp[o + 8 * LP + 8];
            alo[i][0] = *(const uint32_t*)&Ylp[o];
            alo[i][1] = *(const uint32_t*)&Ylp[o + 8 * LP];
            alo[i][2] = *(const uint32_t*)&Ylp[o + 8];
            alo[i][3] = *(const uint32_t*)&Ylp[o + 8 * LP + 8];
        }
        #pragma unroll
        for (int j = 0; j < 8; j++) {
            int o = j * 8 * LP + k2;
            bhi[j][0] = *(const uint32_t*)&Hhp[o];
            bhi[j][1] = *(const uint32_t*)&Hhp[o + 8];
            blo[j][0] = *(const uint32_t*)&Hlp[o];
            blo[j][1] = *(const uint32_t*)&Hlp[o + 8];
        }
        #pragma unroll
        for (int i = 0; i < 2; i++)
            #pragma unroll
            for (int j = 0; j < 8; j++) {
                mma16(d[i][j], ahi[i], bhi[j]);
                mma16(d[i][j], ahi[i], blo[j]);
                mma16(d[i][j], alo[i], bhi[j]);
            }
    }

    // ---- epilogue: per-row tile max/sumexp; store Pu = exp(d - m) ----
    __syncthreads();                 // smem reuse
    float* redm = (float*)smraw;     // [2][128]
    float* reds = redm + 256;        // [2][128]
    int ubase = u0 + wn * 64;

    float mloc[4] = {NEGBIG, NEGBIG, NEGBIG, NEGBIG};
    #pragma unroll
    for (int i = 0; i < 2; i++)
        #pragma unroll
        for (int j = 0; j < 8; j++)
            #pragma unroll
            for (int p = 0; p < 2; p++)
                #pragma unroll
                for (int q = 0; q < 2; q++) {
                    int u = ubase + j * 8 + tg * 2 + q;
                    if (u < Tn)
                        mloc[i * 2 + p] = fmaxf(mloc[i * 2 + p], d[i][j][p * 2 + q]);
                }
    #pragma unroll
    for (int ri = 0; ri < 4; ri++) {
        mloc[ri] = fmaxf(mloc[ri], __shfl_xor_sync(0xffffffffu, mloc[ri], 1));
        mloc[ri] = fmaxf(mloc[ri], __shfl_xor_sync(0xffffffffu, mloc[ri], 2));
    }
    if (tg == 0) {
        #pragma unroll
        for (int ri = 0; ri < 4; ri++) {
            int rl = wm * 32 + (ri >> 1) * 16 + gid + (ri & 1) * 8;
            redm[wn * 128 + rl] = mloc[ri];
        }
    }
    __syncthreads();

    float* Lb = g_L + (size_t)b * CNn * Tn;
    float ssum[4] = {0.f, 0.f, 0.f, 0.f};
    #pragma unroll
    for (int i = 0; i < 2; i++)
        #pragma unroll
        for (int p = 0; p < 2; p++) {
            int ri = i * 2 + p;
            int rl = wm * 32 + i * 16 + gid + p * 8;
            int c  = c0 + rl;
            float m = fmaxf(redm[rl], redm[128 + rl]);
            #pragma unroll
            for (int j = 0; j < 8; j++) {
                int u = ubase + j * 8 + tg * 2;
                float e0 = __expf(d[i][j][p * 2 + 0] - m);
                float e1 = __expf(d[i][j][p * 2 + 1] - m);
                if (u < Tn) {
                    ssum[ri] += e0 + e1;
                    if (c < CNn)
                        *(float2*)&Lb[(size_t)c * Tn + u] = make_float2(e0, e1);
                }
            }
        }
    #pragma unroll
    for (int ri = 0; ri < 4; ri++) {
        ssum[ri] += __shfl_xor_sync(0xffffffffu, ssum[ri], 1);
        ssum[ri] += __shfl_xor_sync(0xffffffffu, ssum[ri], 2);
    }
    if (tg == 0) {
        #pragma unroll
        for (int ri = 0; ri < 4; ri++) {
            int rl = wm * 32 + (ri >> 1) * 16 + gid + (ri & 1) * 8;
            reds[wn * 128 + rl] = ssum[ri];
        }
    }
    __syncthreads();
    if (tid < 128) {
        int c = c0 + tid;
        if (c < CNn) {
            size_t ridx = ((size_t)b * CNn + c) * NUT + ut;
            g_pm[ridx] = fmaxf(redm[tid], redm[128 + tid]);
            g_ps[ridx] = reds[tid] + reds[128 + tid];
        }
    }
}

// ---------------------------------------------------------------------------
// Combine per-tile softmax partials (unchanged)
// ---------------------------------------------------------------------------
__global__ __launch_bounds__(256) void combine_kernel() {
    int idx = blockIdx.x * 256 + threadIdx.x;
    if (idx >= Bn * CNn) return;
    const float* pm = g_pm + (size_t)idx * NUT;
    const float* ps = g_ps + (size_t)idx * NUT;
    float m = NEGBIG;
    #pragma unroll
    for (int t = 0; t < NUT; t++) m = fmaxf(m, pm[t]);
    float s = 0.f;
    #pragma unroll
    for (int t = 0; t < NUT; t++) s += ps[t] * __expf(pm[t] - m);
    g_mx[idx]  = m;
    g_inv[idx] = 1.0f / s;
}

// ===========================================================================
// c_mma_kernel: C = P @ H via mma.sync m16n8k16 FP16 split-3.
// P = Pu * f pre-scaled in fp32, then split. H tile stored TRANSPOSED [h][k]
// so fp16 B-fragments are single half2 loads.
// Block 64c x 192h, BK=32 u; 8 warps (2 c x 4 h), warp 32x48 = 2x6 atoms.
// ===========================================================================
#define LPA 40     // P tile half pitch (32 + 8)
#define LPH 36     // H^T tile half pitch (32 + 4)

__global__ __launch_bounds__(256) void c_mma_kernel(const float* __restrict__ H,
                                                    float* __restrict__ out) {
    __shared__ __half Pshi[64 * LPA];      //  5120 B
    __shared__ __half Pslo[64 * LPA];
    __shared__ __half Hshi[192 * LPH];     // 13824 B
    __shared__ __half Hslo[192 * LPH];
    __shared__ float f_s[64 * NUT];        //  2816 B
    int b  = blockIdx.y;
    int c0 = blockIdx.x * 64;
    int tid = threadIdx.x;
    int wid = tid >> 5, lane = tid & 31, gid = lane >> 2, tg = lane & 3;
    int wm = wid & 1, wn = wid >> 1;       // c: wm*32, h: wn*48

    // correction-factor table
    for (int idx = tid; idx < 64 * NUT; idx += 256) {
        int row = idx / NUT, t = idx - row * NUT;
        int c = c0 + row;
        float f = 0.f;
        if (c < CNn) {
            int rc = b * CNn + c;
            f = __expf(g_pm[(size_t)rc * NUT + t] - g_mx[rc]) * g_inv[rc];
        }
        f_s[idx] = f;
    }
    __syncthreads();

    const float* Lb = g_L + (size_t)b * CNn * Tn;
    const float* Hb = H + (size_t)b * Tn * HDn;
    const float4 z4 = make_float4(0.f, 0.f, 0.f, 0.f);

    float d[2][6][4];
    #pragma unroll
    for (int i = 0; i < 2; i++)
        #pragma unroll
        for (int j = 0; j < 6; j++)
            #pragma unroll
            for (int q = 0; q < 4; q++) d[i][j][q] = 0.f;

    const __half* Php = Pshi + (wm * 32 + gid) * LPA;
    const __half* Plp = Pslo + (wm * 32 + gid) * LPA;
    const __half* Hhp = Hshi + (wn * 48 + gid) * LPH;
    const __half* Hlp = Hslo + (wn * 48 + gid) * LPH;

    #pragma unroll 1
    for (int ch = 0; ch < 44; ch++) {
        int u0c = ch * 32;
        int utt = ch >> 2;
        // fill P tile (64 x 32), scaled then split
        #pragma unroll
        for (int i = 0; i < 2; i++) {
            int idx = tid + 256 * i;         // float4 index, 0..511
            int r = idx >> 3, uu = (idx & 7) * 4;
            int c = c0 + r;
            int u = u0c + uu;
            float4 v = (c < CNn && u < Tn)
                       ? *(const float4*)(Lb + (size_t)c * Tn + u) : z4;
            float f = f_s[r * NUT + utt];
            v.x *= f; v.y *= f; v.z *= f; v.w *= f;
            __half hx, lx, hy, ly, hz, lz, hw, lw;
            split16(v.x, hx, lx); split16(v.y, hy, ly);
            split16(v.z, hz, lz); split16(v.w, hw, lw);
            *(__half2*)&Pshi[r * LPA + uu]     = __halves2half2(hx, hy);
            *(__half2*)&Pshi[r * LPA + uu + 2] = __halves2half2(hz, hw);
            *(__half2*)&Pslo[r * LPA + uu]     = __halves2half2(lx, ly);
            *(__half2*)&Pslo[r * LPA + uu + 2] = __halves2half2(lz, lw);
        }
        // fill H tile TRANSPOSED: Hs[h][k=u'] (32 x 192 source)
        #pragma unroll
        for (int i = 0; i < 6; i++) {
            int idx = tid + 256 * i;         // 0..1535
            int r = idx / 48, hh = (idx % 48) * 4;
            int u = u0c + r;
            float4 w = (u < Tn) ? *(const float4*)(Hb + (size_t)u * HDn + hh) : z4;
            __half hx, lx, hy, ly, hz, lz, hw, lw;
            split16(w.x, hx, lx); split16(w.y, hy, ly);
            split16(w.z, hz, lz); split16(w.w, hw, lw);
            Hshi[(hh + 0) * LPH + r] = hx; Hslo[(hh + 0) * LPH + r] = lx;
            Hshi[(hh + 1) * LPH + r] = hy; Hslo[(hh + 1) * LPH + r] = ly;
            Hshi[(hh + 2) * LPH + r] = hz; Hslo[(hh + 2) * LPH + r] = lz;
            Hshi[(hh + 3) * LPH + r] = hw; Hslo[(hh + 3) * LPH + r] = lw;
        }
        __syncthreads();

        #pragma unroll
        for (int kk = 0; kk < 2; kk++) {
            int k2 = kk * 16 + 2 * tg;
            uint32_t ahi[2][4], alo[2][4], bhi[6][2], blo[6][2];
            #pragma unroll
            for (int i = 0; i < 2; i++) {
                int o = i * 16 * LPA + k2;
                ahi[i][0] = *(const uint32_t*)&Php[o];
                ahi[i][1] = *(const uint32_t*)&Php[o + 8 * LPA];
                ahi[i][2] = *(const uint32_t*)&Php[o + 8];
                ahi[i][3] = *(const uint32_t*)&Php[o + 8 * LPA + 8];
                alo[i][0] = *(const uint32_t*)&Plp[o];
                alo[i][1] = *(const uint32_t*)&Plp[o + 8 * LPA];
                alo[i][2] = *(const uint32_t*)&Plp[o + 8];
                alo[i][3] = *(const uint32_t*)&Plp[o + 8 * LPA + 8];
            }
            #pragma unroll
            for (int j = 0; j < 6; j++) {
                int o = j * 8 * LPH + k2;
                bhi[j][0] = *(const uint32_t*)&Hhp[o];
                bhi[j][1] = *(const uint32_t*)&Hhp[o + 8];
                blo[j][0] = *(const uint32_t*)&Hlp[o];
                blo[j][1] = *(const uint32_t*)&Hlp[o + 8];
            }
            #pragma unroll
            for (int i = 0; i < 2; i++)
                #pragma unroll
                for (int j = 0; j < 6; j++) {
                    mma16(d[i][j], ahi[i], bhi[j]);
                    mma16(d[i][j], ahi[i], blo[j]);
                    mma16(d[i][j], alo[i], bhi[j]);
                }
        }
        __syncthreads();
    }

    // epilogue: direct store (P already normalized)
    #pragma unroll
    for (int i = 0; i < 2; i++)
        #pragma unroll
        for (int p = 0; p < 2; p++) {
            int c = c0 + wm * 32 + i * 16 + gid + p * 8;
            if (c < CNn) {
                float* op = out + ((size_t)b * CNn + c) * HDn;
                #pragma unroll
                for (int j = 0; j < 6; j++) {
                    int h = wn * 48 + j * 8 + tg * 2;
                    *(float2*)&op[h] = make_float2(d[i][j][p * 2 + 0],
                                                   d[i][j][p * 2 + 1]);
                }
            }
        }
}

// ---------------------------------------------------------------------------
extern "C" void kernel_launch(void* const* d_in, const int* in_sizes, int n_in,
                              void* d_out, int out_size) {
    const float* X  = (const float*)d_in[0];
    const float* H  = (const float*)d_in[1];
    const float* W1 = (const float*)d_in[2];
    const float* W2 = (const float*)d_in[3];
    float* out = (float*)d_out;

    cudaFuncSetAttribute(l_mma_kernel,
                         cudaFuncAttributeMaxDynamicSharedMemorySize, LSM_BYTES);

    z_kernel<<<dim3(3, Bn), 256>>>(X, W2);
    y_kernel<<<dim3(44, Bn), 192>>>(W1);
    l_mma_kernel<<<dim3(NUT, 3, Bn), 256, LSM_BYTES>>>(H);
    combine_kernel<<<(Bn * CNn + 255) / 256, 256>>>();
    c_mma_kernel<<<dim3(6, Bn), 256>>>(H, out);
}